// round 15
// baseline (speedup 1.0000x reference)
#include <cuda_runtime.h>
#include <cuda_bf16.h>
#include <math.h>
#include <stdint.h>

// Problem constants
#define BB 2
#define SS 512
#define PP 4096
#define TD 512
#define SD 384
#define HH 8
#define HD 64
#define FF 2048
#define NROW_T (BB*SS)
#define NROW_S (BB*PP)
#define OUT_ELEMS (NROW_T*TD)
#define QELE (BB*HH*SS*HD)
#define KELE (BB*HH*PP*HD)
#define LOG2E 1.44269504088896341f

// ---------------- device scratch ----------------
__device__ uint16_t g_tnh[NROW_T*TD], g_tnl[NROW_T*TD];
__device__ uint16_t g_snh[NROW_S*SD], g_snl[NROW_S*SD];
__device__ uint16_t g_qh[QELE], g_ql[QELE];
__device__ uint16_t g_kh[KELE], g_kl[KELE];
__device__ uint16_t g_vh[KELE], g_vl[KELE];
__device__ uint16_t g_aoh[NROW_T*TD], g_aol[NROW_T*TD];
__device__ uint16_t g_o1h[NROW_T*TD], g_o1l[NROW_T*TD];
__device__ uint16_t g_hidh[NROW_T*FF], g_hidl[NROW_T*FF];
__device__ uint16_t g_wqh[TD*TD], g_wql[TD*TD];
__device__ uint16_t g_wkh[SD*TD], g_wkl[SD*TD];
__device__ uint16_t g_wvh[SD*TD], g_wvl[SD*TD];
__device__ uint16_t g_woh[TD*TD], g_wol[TD*TD];
__device__ uint16_t g_w1h[TD*FF], g_w1l[TD*FF];
__device__ uint16_t g_w2h[FF*TD], g_w2l[FF*TD];
__device__ float g_m2[4*BB*HH*SS];
__device__ float g_z2[4*BB*HH*SS];
__device__ float g_aop[2*NROW_T*TD];
__device__ float g_w2p[4*NROW_T*TD];
__device__ float g_out1[NROW_T*TD];
__device__ float g_tmp[NROW_T*TD];

// ---------------- fast exp2: FFMA/ALU only, magic-number rounding ----------------
// Computes 2^x for x <= ~0 (clamped at -125). ~9 lane-ops.
__device__ __forceinline__ float fexp2(float x) {
    x = fmaxf(x, -125.0f);
    float t = x + 12582912.0f;           // 1.5*2^23: integer part lands in mantissa
    int bi = __float_as_int(t);          // low bits encode round(x)
    float n = t - 12582912.0f;           // round(x) as float
    float f = x - n;                     // fraction in [-0.5, 0.5]
    float p = 1.3333558146e-3f;
    p = fmaf(p, f, 9.6181291076e-3f);
    p = fmaf(p, f, 5.5504108665e-2f);
    p = fmaf(p, f, 2.4022650696e-1f);
    p = fmaf(p, f, 6.9314718056e-1f);
    p = fmaf(p, f, 1.0f);
    // scale = 2^round(x): exponent bits from (bi - bits(12582912) + 127) << 23
    return p * __int_as_float((bi + (127 - 0x4B400000)) << 23);
}

__device__ __forceinline__ void splitv(float v, uint16_t& h, uint16_t& l) {
    __nv_bfloat16 hb = __float2bfloat16(v);
    h = __bfloat16_as_ushort(hb);
    l = __bfloat16_as_ushort(__float2bfloat16(v - __bfloat162float(hb)));
}
__device__ __forceinline__ uint32_t pack2(unsigned short a, unsigned short b) {
    return (uint32_t)a | ((uint32_t)b << 16);
}
__device__ __forceinline__ void split4(float x0, float x1, float x2, float x3,
                                       uint32_t* hi, uint32_t* lo) {
    uint16_t h0,h1,h2,h3,l0,l1,l2,l3;
    splitv(x0,h0,l0); splitv(x1,h1,l1); splitv(x2,h2,l2); splitv(x3,h3,l3);
    hi[0] = pack2(h0,h1); hi[1] = pack2(h2,h3);
    lo[0] = pack2(l0,l1); lo[1] = pack2(l2,l3);
}

// ---------------- cp.async helpers ----------------
__device__ __forceinline__ void cpa16(uint32_t smem, const void* g) {
    asm volatile("cp.async.cg.shared.global [%0], [%1], 16;" :: "r"(smem), "l"(g));
}
__device__ __forceinline__ void cpa_commit() {
    asm volatile("cp.async.commit_group;");
}
__device__ __forceinline__ void cpa_wait0() {
    asm volatile("cp.async.wait_group 0;");
}

// ---------------- LayerNorm (optional 4-way partial-sum + bias input fusion) ------------
__global__ void ln_kernel(const float* __restrict__ x, const float* __restrict__ add,
                          const float* __restrict__ add4, const float* __restrict__ bias2,
                          const float* __restrict__ g, const float* __restrict__ b,
                          float* __restrict__ y, uint16_t* __restrict__ yh,
                          uint16_t* __restrict__ yl, int D) {
    int row = blockIdx.x;
    const float* xr = x + (size_t)row * D;
    const float* ar = add ? add + (size_t)row * D : nullptr;
    const float* a4 = add4 ? add4 + (size_t)row * D : nullptr;

    float s = 0.f, ss = 0.f;
    for (int i = threadIdx.x; i < D; i += blockDim.x) {
        float v = xr[i];
        if (ar) v += ar[i];
        if (a4) v += a4[i] + a4[OUT_ELEMS + i] + a4[2*OUT_ELEMS + i]
                   + a4[3*OUT_ELEMS + i] + bias2[i];
        s += v; ss += v * v;
    }
    __shared__ float sh[66];
    #pragma unroll
    for (int o = 16; o; o >>= 1) {
        s  += __shfl_xor_sync(0xffffffffu, s, o);
        ss += __shfl_xor_sync(0xffffffffu, ss, o);
    }
    int w = threadIdx.x >> 5;
    if ((threadIdx.x & 31) == 0) { sh[w*2] = s; sh[w*2+1] = ss; }
    __syncthreads();
    int nw = blockDim.x >> 5;
    if (threadIdx.x < 32) {
        s  = threadIdx.x < nw ? sh[threadIdx.x*2]   : 0.f;
        ss = threadIdx.x < nw ? sh[threadIdx.x*2+1] : 0.f;
        #pragma unroll
        for (int o = 16; o; o >>= 1) {
            s  += __shfl_xor_sync(0xffffffffu, s, o);
            ss += __shfl_xor_sync(0xffffffffu, ss, o);
        }
        if (threadIdx.x == 0) { sh[64] = s; sh[65] = ss; }
    }
    __syncthreads();
    float mean = sh[64] / (float)D;
    float var  = sh[65] / (float)D - mean * mean;
    float inv  = rsqrtf(var + 1e-5f);
    for (int i = threadIdx.x; i < D; i += blockDim.x) {
        float v = xr[i];
        if (ar) v += ar[i];
        if (a4) v += a4[i] + a4[OUT_ELEMS + i] + a4[2*OUT_ELEMS + i]
                   + a4[3*OUT_ELEMS + i] + bias2[i];
        float o = (v - mean) * inv * g[i] + b[i];
        if (y) y[(size_t)row * D + i] = o;
        if (yh) {
            uint16_t h, l;
            splitv(o, h, l);
            yh[(size_t)row * D + i] = h;
            yl[(size_t)row * D + i] = l;
        }
    }
}

// ---------------- fused weight split ----------------
struct SplitJobs {
    const float* src[6];
    uint16_t* hi[6];
    uint16_t* lo[6];
    int n4[6];
};
__global__ void split_all(SplitJobs jobs) {
    int seg = blockIdx.y;
    int n4 = jobs.n4[seg];
    const float4* src = (const float4*)jobs.src[seg];
    uint2* hid = (uint2*)jobs.hi[seg];
    uint2* lod = (uint2*)jobs.lo[seg];
    for (int i = blockIdx.x * blockDim.x + threadIdx.x; i < n4;
         i += gridDim.x * blockDim.x) {
        float4 f = src[i];
        uint32_t h[2], l[2];
        split4(f.x, f.y, f.z, f.w, h, l);
        hid[i] = make_uint2(h[0], h[1]);
        lod[i] = make_uint2(l[0], l[1]);
    }
}

__global__ void combine_ao(const float* __restrict__ p, uint16_t* __restrict__ aoh,
                           uint16_t* __restrict__ aol, int n) {
    int i = blockIdx.x * blockDim.x + threadIdx.x;
    if (i < n) {
        float v = p[i] + p[n + i];
        uint16_t h, l;
        splitv(v, h, l);
        aoh[i] = h;
        aol[i] = l;
    }
}

// ================== tensor-core primitives ==================
__device__ __forceinline__ void ldsm4(uint32_t& r0, uint32_t& r1, uint32_t& r2, uint32_t& r3,
                                      uint32_t addr) {
    asm volatile("ldmatrix.sync.aligned.m8n8.x4.shared.b16 {%0,%1,%2,%3}, [%4];"
        : "=r"(r0), "=r"(r1), "=r"(r2), "=r"(r3) : "r"(addr));
}
__device__ __forceinline__ void ldsm4t(uint32_t& r0, uint32_t& r1, uint32_t& r2, uint32_t& r3,
                                       uint32_t addr) {
    asm volatile("ldmatrix.sync.aligned.m8n8.x4.trans.shared.b16 {%0,%1,%2,%3}, [%4];"
        : "=r"(r0), "=r"(r1), "=r"(r2), "=r"(r3) : "r"(addr));
}
__device__ __forceinline__ void mma16816(float* c, const uint32_t* a, uint32_t b0, uint32_t b1) {
    asm volatile(
        "mma.sync.aligned.m16n8k16.row.col.f32.bf16.bf16.f32 "
        "{%0,%1,%2,%3},{%4,%5,%6,%7},{%8,%9},{%0,%1,%2,%3};"
        : "+f"(c[0]), "+f"(c[1]), "+f"(c[2]), "+f"(c[3])
        : "r"(a[0]), "r"(a[1]), "r"(a[2]), "r"(a[3]), "r"(b0), "r"(b1));
}

// ============ cp.async 2-stage pre-split GEMM (R11-proven) ============
template<int BM, int MODE>
__global__ __launch_bounds__(256) void mma_gemm_db(
        const uint16_t* __restrict__ Ah, const uint16_t* __restrict__ Al,
        const uint16_t* __restrict__ Wh, const uint16_t* __restrict__ Wl,
        const float* __restrict__ bias, float* __restrict__ Cf,
        uint16_t* __restrict__ Ch, uint16_t* __restrict__ Cl,
        int M, int N, int K, int T) {
    constexpr int BN = 64;
    constexpr int WM = BM / 2;
    constexpr int MT = WM / 16;
    constexpr int NT = 2;
    constexpr int SA = 40, SB = 72;
    constexpr int ATH = BM * 4;

    __shared__ uint16_t As[2][2][BM * SA];
    __shared__ uint16_t Bs[2][2][32 * SB];

    int tid = threadIdx.x;
    int l = tid & 31, w = tid >> 5;
    int wm = w >> 2, wn = w & 3;
    int m0 = blockIdx.y * BM, n0 = blockIdx.x * BN;
    int koff = (MODE == 3) ? blockIdx.z * T : 0;
    int Kloop = (MODE == 3) ? T : K;

    int arow = tid >> 2, aseg = (tid & 3) * 8;
    int bk = tid >> 3, bn = (tid & 7) * 8;

    uint32_t asb[2][2], bsb[2][2];
    #pragma unroll
    for (int s = 0; s < 2; s++) {
        #pragma unroll
        for (int p = 0; p < 2; p++) {
            asb[s][p] = (uint32_t)__cvta_generic_to_shared(&As[s][p][0]);
            bsb[s][p] = (uint32_t)__cvta_generic_to_shared(&Bs[s][p][0]);
        }
    }
    uint32_t aoff = (uint32_t)((arow * SA + aseg) * 2);
    uint32_t boff = (uint32_t)((bk * SB + bn) * 2);

    uint32_t aAddr[MT];
    #pragma unroll
    for (int mt = 0; mt < MT; mt++) {
        int row = wm * WM + mt * 16 + (l & 15);
        aAddr[mt] = (uint32_t)((row * SA + (l >> 4) * 8) * 2);
    }
    uint32_t bAddr;
    {
        int kk = (l & 7) + ((l >> 3) & 1) * 8;
        int nn = wn * 16 + (l >> 4) * 8;
        bAddr = (uint32_t)((kk * SB + nn) * 2);
    }

    float acc[MT][NT][4];
    #pragma unroll
    for (int mt = 0; mt < MT; mt++)
        #pragma unroll
        for (int nt = 0; nt < NT; nt++)
            #pragma unroll
            for (int i = 0; i < 4; i++) acc[mt][nt][i] = 0.f;

    auto issue = [&](int stage, int k0) {
        if (ATH == 256 || tid < ATH) {
            cpa16(asb[stage][0] + aoff, Ah + (size_t)(m0 + arow) * K + koff + k0 + aseg);
            cpa16(asb[stage][1] + aoff, Al + (size_t)(m0 + arow) * K + koff + k0 + aseg);
        }
        cpa16(bsb[stage][0] + boff, Wh + (size_t)(koff + k0 + bk) * N + n0 + bn);
        cpa16(bsb[stage][1] + boff, Wl + (size_t)(koff + k0 + bk) * N + n0 + bn);
        cpa_commit();
    };

    int nch = Kloop / 32;
    issue(0, 0);
    for (int c = 0; c < nch; c++) {
        cpa_wait0();
        __syncthreads();
        if (c + 1 < nch) issue((c + 1) & 1, (c + 1) * 32);
        int st = c & 1;

        #pragma unroll
        for (int ks = 0; ks < 32; ks += 16) {
            uint32_t aHi[MT][4], aLo[MT][4];
            #pragma unroll
            for (int mt = 0; mt < MT; mt++) {
                ldsm4(aHi[mt][0], aHi[mt][1], aHi[mt][2], aHi[mt][3],
                      asb[st][0] + aAddr[mt] + ks * 2);
                ldsm4(aLo[mt][0], aLo[mt][1], aLo[mt][2], aLo[mt][3],
                      asb[st][1] + aAddr[mt] + ks * 2);
            }
            uint32_t bh[4], bl[4];
            ldsm4t(bh[0], bh[1], bh[2], bh[3], bsb[st][0] + bAddr + ks * SB * 2);
            ldsm4t(bl[0], bl[1], bl[2], bl[3], bsb[st][1] + bAddr + ks * SB * 2);
            #pragma unroll
            for (int q = 0; q < 2; q++) {
                #pragma unroll
                for (int mt = 0; mt < MT; mt++) {
                    mma16816(acc[mt][q], aHi[mt], bh[2*q], bh[2*q+1]);
                    mma16816(acc[mt][q], aHi[mt], bl[2*q], bl[2*q+1]);
                    mma16816(acc[mt][q], aLo[mt], bh[2*q], bh[2*q+1]);
                }
            }
        }
        __syncthreads();
    }

    #pragma unroll
    for (int mt = 0; mt < MT; mt++) {
        int row0 = m0 + wm * WM + mt * 16 + (l >> 2);
        #pragma unroll
        for (int nt = 0; nt < NT; nt++) {
            int col = n0 + wn * 16 + nt * 8 + (l & 3) * 2;
            if (MODE == 3) {
                float* dst = Cf + (size_t)blockIdx.z * M * N;
                *(float2*)(dst + (size_t)row0 * N + col) =
                    make_float2(acc[mt][nt][0], acc[mt][nt][1]);
                *(float2*)(dst + (size_t)(row0 + 8) * N + col) =
                    make_float2(acc[mt][nt][2], acc[mt][nt][3]);
                continue;
            }
            float b0 = bias[col], b1 = bias[col + 1];
            float v00 = acc[mt][nt][0] + b0, v01 = acc[mt][nt][1] + b1;
            float v10 = acc[mt][nt][2] + b0, v11 = acc[mt][nt][3] + b1;
            if (MODE == 2) {
                v00 = 0.5f * v00 * (1.f + erff(v00 * 0.70710678118654752f));
                v01 = 0.5f * v01 * (1.f + erff(v01 * 0.70710678118654752f));
                v10 = 0.5f * v10 * (1.f + erff(v10 * 0.70710678118654752f));
                v11 = 0.5f * v11 * (1.f + erff(v11 * 0.70710678118654752f));
            }
            if (MODE == 0) {
                *(float2*)(Cf + (size_t)row0 * N + col)       = make_float2(v00, v01);
                *(float2*)(Cf + (size_t)(row0 + 8) * N + col) = make_float2(v10, v11);
            } else {
                uint16_t h00,l00,h01,l01,h10,l10,h11,l11;
                splitv(v00,h00,l00); splitv(v01,h01,l01);
                splitv(v10,h10,l10); splitv(v11,h11,l11);
                size_t i0x, i1x;
                if (MODE == 1) {
                    int h = col >> 6, d = col & 63;
                    int bi0 = row0 / T, t0 = row0 % T;
                    int bi1 = (row0 + 8) / T, t1 = (row0 + 8) % T;
                    i0x = (size_t)((bi0*HH + h)*T + t0)*HD + d;
                    i1x = (size_t)((bi1*HH + h)*T + t1)*HD + d;
                } else {
                    i0x = (size_t)row0 * N + col;
                    i1x = (size_t)(row0 + 8) * N + col;
                }
                *(ushort2*)(Ch + i0x) = make_ushort2(h00, h01);
                *(ushort2*)(Cl + i0x) = make_ushort2(l00, l01);
                *(ushort2*)(Ch + i1x) = make_ushort2(h10, h11);
                *(ushort2*)(Cl + i1x) = make_ushort2(l10, l11);
            }
        }
    }
}

// ================== attention pass A (jz x4; logits stored in log2 domain) ==============
__global__ __launch_bounds__(256) void attn_scores_mma(
        const uint16_t* __restrict__ qh, const uint16_t* __restrict__ ql,
        const uint16_t* __restrict__ kh_, const uint16_t* __restrict__ kl_,
        const float* __restrict__ edge_emb, const float* __restrict__ ep_w,
        const float* __restrict__ ep_b,
        float* __restrict__ logits, float* __restrict__ gm2, float* __restrict__ gz2) {
    __shared__ uint16_t Qhi[64*72], Qlo[64*72];
    __shared__ uint16_t Khi[64*72], Klo[64*72];
    __shared__ float m_sh[2][64], l_sh[2][64];
    __shared__ float s_scale;

    int tid = threadIdx.x, l = tid & 31, w = tid >> 5;
    int wm = w >> 1, wn = w & 1;
    int bh = blockIdx.y, i0 = blockIdx.x * 64;
    int jz = blockIdx.z;
    int hidx = bh & (HH-1);
    const uint16_t* qhb = qh + ((size_t)bh * SS + i0) * HD;
    const uint16_t* qlb = ql + ((size_t)bh * SS + i0) * HD;
    const uint16_t* khb = kh_ + (size_t)bh * PP * HD;
    const uint16_t* klb = kl_ + (size_t)bh * PP * HD;
    float* lb = logits + ((size_t)bh * SS + i0) * PP;
    float epb = ep_b[0];

    if (tid < 32) {
        float a = edge_emb[hidx*32 + tid] * ep_w[tid];
        #pragma unroll
        for (int o = 16; o; o >>= 1) a += __shfl_xor_sync(0xffffffffu, a, o);
        if (tid == 0) s_scale = a;
    }

    int lrow = tid >> 2, lseg = (tid & 3) * 16;
    {
        const uint16_t* s = qhb + (size_t)lrow * HD + lseg;
        *(uint4*)&Qhi[lrow*72 + lseg]     = *(const uint4*)(s);
        *(uint4*)&Qhi[lrow*72 + lseg + 8] = *(const uint4*)(s + 8);
        s = qlb + (size_t)lrow * HD + lseg;
        *(uint4*)&Qlo[lrow*72 + lseg]     = *(const uint4*)(s);
        *(uint4*)&Qlo[lrow*72 + lseg + 8] = *(const uint4*)(s + 8);
    }

    uint32_t aHiB = (uint32_t)__cvta_generic_to_shared(Qhi);
    uint32_t aLoB = (uint32_t)__cvta_generic_to_shared(Qlo);
    uint32_t bHiB = (uint32_t)__cvta_generic_to_shared(Khi);
    uint32_t bLoB = (uint32_t)__cvta_generic_to_shared(Klo);

    uint32_t aAddr = (uint32_t)(((wm*16 + (l & 15)) * 72 + (l >> 4) * 8) * 2);
    uint32_t bAddr[2];
    #pragma unroll
    for (int p = 0; p < 2; p++)
        bAddr[p] = (uint32_t)(((wn*32 + p*16 + (l & 15)) * 72 + (l >> 4) * 8) * 2);

    float m_run[2] = {-1e30f, -1e30f};
    float l_run[2] = {0.f, 0.f};

    int jstart = jz * (PP/4), jend = (jz + 1) * (PP/4);

    uint4 rh0, rh1, rl0, rl1;
    {
        const uint16_t* s = khb + (size_t)(jstart + lrow) * HD + lseg;
        rh0 = *(const uint4*)(s); rh1 = *(const uint4*)(s + 8);
        s = klb + (size_t)(jstart + lrow) * HD + lseg;
        rl0 = *(const uint4*)(s); rl1 = *(const uint4*)(s + 8);
    }

    for (int j0 = jstart; j0 < jend; j0 += 64) {
        __syncthreads();
        *(uint4*)&Khi[lrow*72 + lseg]     = rh0;
        *(uint4*)&Khi[lrow*72 + lseg + 8] = rh1;
        *(uint4*)&Klo[lrow*72 + lseg]     = rl0;
        *(uint4*)&Klo[lrow*72 + lseg + 8] = rl1;
        __syncthreads();
        if (j0 + 64 < jend) {
            const uint16_t* s = khb + (size_t)(j0 + 64 + lrow) * HD + lseg;
            rh0 = *(const uint4*)(s); rh1 = *(const uint4*)(s + 8);
            s = klb + (size_t)(j0 + 64 + lrow) * HD + lseg;
            rl0 = *(const uint4*)(s); rl1 = *(const uint4*)(s + 8);
        }

        float acc[4][4];
        #pragma unroll
        for (int nt = 0; nt < 4; nt++)
            #pragma unroll
            for (int i = 0; i < 4; i++) acc[nt][i] = 0.f;

        #pragma unroll
        for (int ks = 0; ks < 64; ks += 16) {
            uint32_t ah[4], al[4];
            ldsm4(ah[0], ah[1], ah[2], ah[3], aHiB + aAddr + ks * 2);
            ldsm4(al[0], al[1], al[2], al[3], aLoB + aAddr + ks * 2);
            #pragma unroll
            for (int p = 0; p < 2; p++) {
                uint32_t kh[4], kl[4];
                ldsm4(kh[0], kh[1], kh[2], kh[3], bHiB + bAddr[p] + ks * 2);
                ldsm4(kl[0], kl[1], kl[2], kl[3], bLoB + bAddr[p] + ks * 2);
                mma16816(acc[2*p],   ah, kh[0], kh[2]);
                mma16816(acc[2*p],   ah, kl[0], kl[2]);
                mma16816(acc[2*p],   al, kh[0], kh[2]);
                mma16816(acc[2*p+1], ah, kh[1], kh[3]);
                mma16816(acc[2*p+1], ah, kl[1], kl[3]);
                mma16816(acc[2*p+1], al, kh[1], kh[3]);
            }
        }

        float sh_scale = s_scale;
        int r0 = wm*16 + (l >> 2);
        #pragma unroll
        for (int nt = 0; nt < 4; nt++) {
            int noff = wn*32 + (nt >> 1)*16 + (nt & 1)*8 + (l & 3)*2;
            #pragma unroll
            for (int i = 0; i < 4; i++) {
                float sc = acc[nt][i] * 0.125f;
                float t = fmaf(sc, sh_scale, epb);
                acc[nt][i] = (sc + (t > 0.f ? t : 0.2f * t)) * LOG2E;  // log2-domain
            }
            *(float2*)(lb + (size_t)r0 * PP + j0 + noff)       = make_float2(acc[nt][0], acc[nt][1]);
            *(float2*)(lb + (size_t)(r0 + 8) * PP + j0 + noff) = make_float2(acc[nt][2], acc[nt][3]);
        }
        #pragma unroll
        for (int r = 0; r < 2; r++) {
            float tm = -1e30f;
            #pragma unroll
            for (int nt = 0; nt < 4; nt++)
                tm = fmaxf(tm, fmaxf(acc[nt][2*r], acc[nt][2*r+1]));
            tm = fmaxf(tm, __shfl_xor_sync(0xffffffffu, tm, 1));
            tm = fmaxf(tm, __shfl_xor_sync(0xffffffffu, tm, 2));
            float nm = fmaxf(m_run[r], tm);
            float pe = 0.f;
            #pragma unroll
            for (int nt = 0; nt < 4; nt++)
                pe += fexp2(acc[nt][2*r] - nm) + fexp2(acc[nt][2*r+1] - nm);
            pe += __shfl_xor_sync(0xffffffffu, pe, 1);
            pe += __shfl_xor_sync(0xffffffffu, pe, 2);
            l_run[r] = l_run[r] * fexp2(m_run[r] - nm) + pe;
            m_run[r] = nm;
        }
    }

    if ((l & 3) == 0) {
        int r0 = wm*16 + (l >> 2);
        m_sh[wn][r0]   = m_run[0];  l_sh[wn][r0]   = l_run[0];
        m_sh[wn][r0+8] = m_run[1];  l_sh[wn][r0+8] = l_run[1];
    }
    __syncthreads();
    if (tid < 64) {
        float m0 = m_sh[0][tid], m1 = m_sh[1][tid];
        float M = fmaxf(m0, m1);
        float Z = l_sh[0][tid] * fexp2(m0 - M) + l_sh[1][tid] * fexp2(m1 - M);
        size_t idx = (size_t)jz * (BB*HH*SS) + (size_t)bh*SS + i0 + tid;
        gm2[idx] = M;
        gz2[idx] = Z;
    }
}

// ================== attention pass B (j-split x2; reads log2-domain logits) ==============
__global__ __launch_bounds__(256) void attn_pv_mma(
        const uint16_t* __restrict__ vh_, const uint16_t* __restrict__ vl_,
        const float* __restrict__ gm2, const float* __restrict__ gz2,
        float* __restrict__ attn, float* __restrict__ aop) {
    __shared__ uint16_t Phi[32*72], Plo[32*72];
    __shared__ uint16_t Vhi[64*72], Vlo[64*72];
    __shared__ float sm_m[32], sm_iz[32];

    int tid = threadIdx.x, l = tid & 31, w = tid >> 5;
    int wm = w >> 2, wn = w & 3;
    int bh = blockIdx.y;
    int b = bh >> 3, h = bh & 7;
    int i0 = blockIdx.x * 32;
    int jz = blockIdx.z;
    float* ab = attn + ((size_t)bh * SS + i0) * PP;
    const uint16_t* vhb = vh_ + (size_t)bh * PP * HD;
    const uint16_t* vlb = vl_ + (size_t)bh * PP * HD;

    if (tid < 32) {
        size_t idx = (size_t)bh*SS + i0 + tid;
        const size_t STR = (size_t)(BB*HH*SS);
        float m0 = gm2[idx], m1 = gm2[STR + idx];
        float m2 = gm2[2*STR + idx], m3 = gm2[3*STR + idx];
        float M = fmaxf(fmaxf(m0, m1), fmaxf(m2, m3));
        float Z = gz2[idx] * fexp2(m0 - M) + gz2[STR + idx] * fexp2(m1 - M)
                + gz2[2*STR + idx] * fexp2(m2 - M) + gz2[3*STR + idx] * fexp2(m3 - M);
        sm_m[tid]  = M;
        sm_iz[tid] = 1.f / Z;
    }

    uint32_t aHiB = (uint32_t)__cvta_generic_to_shared(Phi);
    uint32_t aLoB = (uint32_t)__cvta_generic_to_shared(Plo);
    uint32_t bHiB = (uint32_t)__cvta_generic_to_shared(Vhi);
    uint32_t bLoB = (uint32_t)__cvta_generic_to_shared(Vlo);

    uint32_t aAddr = (uint32_t)(((wm*16 + (l & 15)) * 72 + (l >> 4) * 8) * 2);
    uint32_t bAddr;
    {
        int kk = (l & 7) + ((l >> 3) & 1) * 8;
        int nn = wn*16 + (l >> 4) * 8;
        bAddr = (uint32_t)((kk * 72 + nn) * 2);
    }

    float acc[2][4];
    #pragma unroll
    for (int q = 0; q < 2; q++)
        #pragma unroll
        for (int i = 0; i < 4; i++) acc[q][i] = 0.f;

    int prow = tid >> 3, pseg = (tid & 7) * 8;
    int vrow = tid >> 2, vseg = (tid & 3) * 16;

    int jstart = jz * (PP/2), jend = (jz + 1) * (PP/2);

    float4 pf0, pf1;
    uint4 rvh0, rvh1, rvl0, rvl1;
    {
        const float* src = ab + (size_t)prow * PP + jstart + pseg;
        pf0 = *(const float4*)(src);
        pf1 = *(const float4*)(src + 4);
        const uint16_t* s = vhb + (size_t)(jstart + vrow) * HD + vseg;
        rvh0 = *(const uint4*)(s); rvh1 = *(const uint4*)(s + 8);
        s = vlb + (size_t)(jstart + vrow) * HD + vseg;
        rvl0 = *(const uint4*)(s); rvl1 = *(const uint4*)(s + 8);
    }

    for (int j0 = jstart; j0 < jend; j0 += 64) {
        __syncthreads();
        {
            float m = sm_m[prow], iz = sm_iz[prow];
            float pv[8];
            pv[0] = fexp2(pf0.x - m) * iz; pv[1] = fexp2(pf0.y - m) * iz;
            pv[2] = fexp2(pf0.z - m) * iz; pv[3] = fexp2(pf0.w - m) * iz;
            pv[4] = fexp2(pf1.x - m) * iz; pv[5] = fexp2(pf1.y - m) * iz;
            pv[6] = fexp2(pf1.z - m) * iz; pv[7] = fexp2(pf1.w - m) * iz;
            float* dst = ab + (size_t)prow * PP + j0 + pseg;
            *(float4*)(dst)     = make_float4(pv[0], pv[1], pv[2], pv[3]);
            *(float4*)(dst + 4) = make_float4(pv[4], pv[5], pv[6], pv[7]);
            uint32_t hi[4], lo[4];
            split4(pv[0], pv[1], pv[2], pv[3], hi,     lo);
            split4(pv[4], pv[5], pv[6], pv[7], hi + 2, lo + 2);
            *(uint4*)&Phi[prow*72 + pseg] = *(uint4*)hi;
            *(uint4*)&Plo[prow*72 + pseg] = *(uint4*)lo;
        }
        *(uint4*)&Vhi[vrow*72 + vseg]     = rvh0;
        *(uint4*)&Vhi[vrow*72 + vseg + 8] = rvh1;
        *(uint4*)&Vlo[vrow*72 + vseg]     = rvl0;
        *(uint4*)&Vlo[vrow*72 + vseg + 8] = rvl1;
        __syncthreads();
        if (j0 + 64 < jend) {
            const float* src = ab + (size_t)prow * PP + j0 + 64 + pseg;
            pf0 = *(const float4*)(src);
            pf1 = *(const float4*)(src + 4);
            const uint16_t* s = vhb + (size_t)(j0 + 64 + vrow) * HD + vseg;
            rvh0 = *(const uint4*)(s); rvh1 = *(const uint4*)(s + 8);
            s = vlb + (size_t)(j0 + 64 + vrow) * HD + vseg;
            rvl0 = *(const uint4*)(s); rvl1 = *(const uint4*)(s + 8);
        }

        #pragma unroll
        for (int ks = 0; ks < 64; ks += 16) {
            uint32_t ah[4], al[4];
            ldsm4(ah[0], ah[1], ah[2], ah[3], aHiB + aAddr + ks * 2);
            ldsm4(al[0], al[1], al[2], al[3], aLoB + aAddr + ks * 2);
            uint32_t vh[4], vl[4];
            ldsm4t(vh[0], vh[1], vh[2], vh[3], bHiB + bAddr + ks * 72 * 2);
            ldsm4t(vl[0], vl[1], vl[2], vl[3], bLoB + bAddr + ks * 72 * 2);
            #pragma unroll
            for (int q = 0; q < 2; q++) {
                mma16816(acc[q], ah, vh[2*q], vh[2*q+1]);
                mma16816(acc[q], ah, vl[2*q], vl[2*q+1]);
                mma16816(acc[q], al, vh[2*q], vh[2*q+1]);
            }
        }
    }

    float* dst = aop + (size_t)jz * OUT_ELEMS;
    int r0 = i0 + wm*16 + (l >> 2);
    #pragma unroll
    for (int q = 0; q < 2; q++) {
        int col = h*HD + wn*16 + q*8 + (l & 3)*2;
        *(float2*)(dst + (size_t)(b*SS + r0) * TD + col)     = make_float2(acc[q][0], acc[q][1]);
        *(float2*)(dst + (size_t)(b*SS + r0 + 8) * TD + col) = make_float2(acc[q][2], acc[q][3]);
    }
}

// ---------------- launch ----------------
extern "C" void kernel_launch(void* const* d_in, const int* in_sizes, int n_in,
                              void* d_out, int out_size) {
    const float* text  = (const float*)d_in[0];
    const float* shape = (const float*)d_in[1];
    const float* tn_g = (const float*)d_in[2];
    const float* tn_b = (const float*)d_in[3];
    const float* sn_g = (const float*)d_in[4];
    const float* sn_b = (const float*)d_in[5];
    const float* Wq = (const float*)d_in[6];
    const float* bq = (const float*)d_in[7];
    const float* Wk = (const float*)d_in[8];
    const float* bk = (const float*)d_in[9];
    const float* Wv = (const float*)d_in[10];
    const float* bv = (const float*)d_in[11];
    const float* edge_emb = (const float*)d_in[12];
    const float* ep_w = (const float*)d_in[13];
    const float* ep_b = (const float*)d_in[14];
    const float* Wo = (const float*)d_in[15];
    const float* bo = (const float*)d_in[16];
    const float* on_g = (const float*)d_in[17];
    const float* on_b = (const float*)d_in[18];
    const float* W1 = (const float*)d_in[19];
    const float* b1 = (const float*)d_in[20];
    const float* W2 = (const float*)d_in[21];
    const float* b2 = (const float*)d_in[22];
    const float* fn_g = (const float*)d_in[23];
    const float* fn_b = (const float*)d_in[24];

    float* out_final = (float*)d_out;
    float* attn_buf  = (float*)d_out + OUT_ELEMS;

    uint16_t *p_tnh,*p_tnl,*p_snh,*p_snl,*p_qh,*p_ql,*p_kh,*p_kl,*p_vh,*p_vl;
    uint16_t *p_aoh,*p_aol,*p_o1h,*p_o1l,*p_hidh,*p_hidl;
    uint16_t *p_wqh,*p_wql,*p_wkh,*p_wkl,*p_wvh,*p_wvl,*p_woh,*p_wol,*p_w1h,*p_w1l,*p_w2h,*p_w2l;
    float *p_m2,*p_z2,*p_o1,*p_tmp,*p_aop,*p_w2p;
    cudaGetSymbolAddress((void**)&p_tnh, g_tnh); cudaGetSymbolAddress((void**)&p_tnl, g_tnl);
    cudaGetSymbolAddress((void**)&p_snh, g_snh); cudaGetSymbolAddress((void**)&p_snl, g_snl);
    cudaGetSymbolAddress((void**)&p_qh, g_qh);   cudaGetSymbolAddress((void**)&p_ql, g_ql);
    cudaGetSymbolAddress((void**)&p_kh, g_kh);   cudaGetSymbolAddress((void**)&p_kl, g_kl);
    cudaGetSymbolAddress((void**)&p_vh, g_vh);   cudaGetSymbolAddress((void**)&p_vl, g_vl);
    cudaGetSymbolAddress((void**)&p_aoh, g_aoh); cudaGetSymbolAddress((void**)&p_aol, g_aol);
    cudaGetSymbolAddress((void**)&p_o1h, g_o1h); cudaGetSymbolAddress((void**)&p_o1l, g_o1l);
    cudaGetSymbolAddress((void**)&p_hidh, g_hidh); cudaGetSymbolAddress((void**)&p_hidl, g_hidl);
    cudaGetSymbolAddress((void**)&p_wqh, g_wqh); cudaGetSymbolAddress((void**)&p_wql, g_wql);
    cudaGetSymbolAddress((void**)&p_wkh, g_wkh); cudaGetSymbolAddress((void**)&p_wkl, g_wkl);
    cudaGetSymbolAddress((void**)&p_wvh, g_wvh); cudaGetSymbolAddress((void**)&p_wvl, g_wvl);
    cudaGetSymbolAddress((void**)&p_woh, g_woh); cudaGetSymbolAddress((void**)&p_wol, g_wol);
    cudaGetSymbolAddress((void**)&p_w1h, g_w1h); cudaGetSymbolAddress((void**)&p_w1l, g_w1l);
    cudaGetSymbolAddress((void**)&p_w2h, g_w2h); cudaGetSymbolAddress((void**)&p_w2l, g_w2l);
    cudaGetSymbolAddress((void**)&p_m2, g_m2);   cudaGetSymbolAddress((void**)&p_z2, g_z2);
    cudaGetSymbolAddress((void**)&p_o1, g_out1); cudaGetSymbolAddress((void**)&p_tmp, g_tmp);
    cudaGetSymbolAddress((void**)&p_aop, g_aop); cudaGetSymbolAddress((void**)&p_w2p, g_w2p);

    static cudaStream_t s1 = nullptr, s2 = nullptr;
    static cudaEvent_t ev[6];
    if (!s1) {
        cudaStreamCreateWithFlags(&s1, cudaStreamNonBlocking);
        cudaStreamCreateWithFlags(&s2, cudaStreamNonBlocking);
        for (int i = 0; i < 6; i++)
            cudaEventCreateWithFlags(&ev[i], cudaEventDisableTiming);
    }

    SplitJobs jobs;
    jobs.src[0]=Wq; jobs.hi[0]=p_wqh; jobs.lo[0]=p_wql; jobs.n4[0]=TD*TD/4;
    jobs.src[1]=Wk; jobs.hi[1]=p_wkh; jobs.lo[1]=p_wkl; jobs.n4[1]=SD*TD/4;
    jobs.src[2]=Wv; jobs.hi[2]=p_wvh; jobs.lo[2]=p_wvl; jobs.n4[2]=SD*TD/4;
    jobs.src[3]=Wo; jobs.hi[3]=p_woh; jobs.lo[3]=p_wol; jobs.n4[3]=TD*TD/4;
    jobs.src[4]=W1; jobs.hi[4]=p_w1h; jobs.lo[4]=p_w1l; jobs.n4[4]=TD*FF/4;
    jobs.src[5]=W2; jobs.hi[5]=p_w2h; jobs.lo[5]=p_w2l; jobs.n4[5]=FF*TD/4;

    // ---- fork 1: weight split (0) || ln text (s1) || ln shape (s2) ----
    cudaEventRecord(ev[0], 0);
    cudaStreamWaitEvent(s1, ev[0], 0);
    cudaStreamWaitEvent(s2, ev[0], 0);
    split_all<<<dim3(256, 6), 256, 0, 0>>>(jobs);
    ln_kernel<<<NROW_T, 128, 0, s1>>>(text, nullptr, nullptr, nullptr,
                                      tn_g, tn_b, nullptr, p_tnh, p_tnl, TD);
    ln_kernel<<<NROW_S, 128, 0, s2>>>(shape, nullptr, nullptr, nullptr,
                                      sn_g, sn_b, nullptr, p_snh, p_snl, SD);
    cudaEventRecord(ev[1], s1);
    cudaEventRecord(ev[2], s2);
    cudaStreamWaitEvent(0, ev[1], 0);
    cudaStreamWaitEvent(0, ev[2], 0);

    // ---- fork 2: Q (0) || K (s1) || V (s2) ----
    cudaEventRecord(ev[3], 0);
    cudaStreamWaitEvent(s1, ev[3], 0);
    cudaStreamWaitEvent(s2, ev[3], 0);
    mma_gemm_db<32,1><<<dim3(TD/64, NROW_T/32), 256, 0, 0>>>(
        p_tnh, p_tnl, p_wqh, p_wql, bq, nullptr, p_qh, p_ql, NROW_T, TD, TD, SS);
    mma_gemm_db<64,1><<<dim3(TD/64, NROW_S/64), 256, 0, s1>>>(
        p_snh, p_snl, p_wkh, p_wkl, bk, nullptr, p_kh, p_kl, NROW_S, TD, SD, PP);
    mma_gemm_db<64,1><<<dim3(TD/64, NROW_S/64), 256, 0, s2>>>(
        p_snh, p_snl, p_wvh, p_wvl, bv, nullptr, p_vh, p_vl, NROW_S, TD, SD, PP);
    cudaEventRecord(ev[4], s1);
    cudaEventRecord(ev[5], s2);

    // ---- pass A needs Q (stream 0) + K ----
    cudaStreamWaitEvent(0, ev[4], 0);
    attn_scores_mma<<<dim3(SS/64, BB*HH, 4), 256, 0, 0>>>(p_qh, p_ql, p_kh, p_kl,
                                                          edge_emb, ep_w, ep_b,
                                                          attn_buf, p_m2, p_z2);
    // ---- pass B additionally needs V ----
    cudaStreamWaitEvent(0, ev[5], 0);
    attn_pv_mma<<<dim3(SS/32, BB*HH, 2), 256, 0, 0>>>(p_vh, p_vl, p_m2, p_z2, attn_buf, p_aop);
    combine_ao<<<(OUT_ELEMS + 255)/256, 256, 0, 0>>>(p_aop, p_aoh, p_aol, OUT_ELEMS);

    // ---- serial tail ----
    mma_gemm_db<32,0><<<dim3(TD/64, NROW_T/32), 256, 0, 0>>>(
        p_aoh, p_aol, p_woh, p_wol, bo, p_tmp, nullptr, nullptr, NROW_T, TD, TD, 0);
    ln_kernel<<<NROW_T, 128, 0, 0>>>(text, p_tmp, nullptr, nullptr,
                                     on_g, on_b, p_o1, p_o1h, p_o1l, TD);

    mma_gemm_db<32,2><<<dim3(FF/64, NROW_T/32), 256, 0, 0>>>(
        p_o1h, p_o1l, p_w1h, p_w1l, b1, nullptr, p_hidh, p_hidl, NROW_T, FF, TD, 0);
    mma_gemm_db<32,3><<<dim3(TD/64, NROW_T/32, 4), 256, 0, 0>>>(
        p_hidh, p_hidl, p_w2h, p_w2l, b2, p_w2p, nullptr, nullptr, NROW_T, TD, FF, FF/4);
    // final LN fuses the 4-way W2 partial combine + b2 + residual(o1)
    ln_kernel<<<NROW_T, 128, 0, 0>>>(p_o1, nullptr, p_w2p, b2,
                                     fn_g, fn_b, out_final, nullptr, nullptr, TD);
}

// round 16
// speedup vs baseline: 1.0335x; 1.0335x over previous
#include <cuda_runtime.h>
#include <cuda_bf16.h>
#include <math.h>
#include <stdint.h>

// Problem constants
#define BB 2
#define SS 512
#define PP 4096
#define TD 512
#define SD 384
#define HH 8
#define HD 64
#define FF 2048
#define NROW_T (BB*SS)
#define NROW_S (BB*PP)
#define OUT_ELEMS (NROW_T*TD)
#define QELE (BB*HH*SS*HD)
#define KELE (BB*HH*PP*HD)

// ---------------- device scratch ----------------
__device__ uint16_t g_tnh[NROW_T*TD], g_tnl[NROW_T*TD];
__device__ uint16_t g_snh[NROW_S*SD], g_snl[NROW_S*SD];
__device__ uint16_t g_qh[QELE], g_ql[QELE];
__device__ uint16_t g_kh[KELE], g_kl[KELE];
__device__ uint16_t g_vh[KELE], g_vl[KELE];
__device__ uint16_t g_aoh[NROW_T*TD], g_aol[NROW_T*TD];
__device__ uint16_t g_o1h[NROW_T*TD], g_o1l[NROW_T*TD];
__device__ uint16_t g_hidh[NROW_T*FF], g_hidl[NROW_T*FF];
__device__ uint16_t g_wqh[TD*TD], g_wql[TD*TD];
__device__ uint16_t g_wkh[SD*TD], g_wkl[SD*TD];
__device__ uint16_t g_wvh[SD*TD], g_wvl[SD*TD];
__device__ uint16_t g_woh[TD*TD], g_wol[TD*TD];
__device__ uint16_t g_w1h[TD*FF], g_w1l[TD*FF];
__device__ uint16_t g_w2h[FF*TD], g_w2l[FF*TD];
__device__ float g_m2[4*BB*HH*SS];
__device__ float g_z2[4*BB*HH*SS];
__device__ float g_aop[2*NROW_T*TD];
__device__ float g_w2p[4*NROW_T*TD];
__device__ float g_out1[NROW_T*TD];
__device__ float g_tmp[NROW_T*TD];

// ---------------- fast exp (FFMA/ALU only; R12-proven) ----------------
__device__ __forceinline__ float fexp(float x) {
    x = fmaxf(x, -87.0f);
    float t = x * 1.44269504088896341f;
    float r = rintf(t);
    float f = t - r;
    float p = 1.3333558146e-3f;
    p = fmaf(p, f, 9.6181291076e-3f);
    p = fmaf(p, f, 5.5504108665e-2f);
    p = fmaf(p, f, 2.4022650696e-1f);
    p = fmaf(p, f, 6.9314718056e-1f);
    p = fmaf(p, f, 1.0f);
    int i = (int)r;
    return p * __int_as_float((i + 127) << 23);
}

__device__ __forceinline__ void splitv(float v, uint16_t& h, uint16_t& l) {
    __nv_bfloat16 hb = __float2bfloat16(v);
    h = __bfloat16_as_ushort(hb);
    l = __bfloat16_as_ushort(__float2bfloat16(v - __bfloat162float(hb)));
}
__device__ __forceinline__ uint32_t pack2(unsigned short a, unsigned short b) {
    return (uint32_t)a | ((uint32_t)b << 16);
}
__device__ __forceinline__ void split4(float x0, float x1, float x2, float x3,
                                       uint32_t* hi, uint32_t* lo) {
    uint16_t h0,h1,h2,h3,l0,l1,l2,l3;
    splitv(x0,h0,l0); splitv(x1,h1,l1); splitv(x2,h2,l2); splitv(x3,h3,l3);
    hi[0] = pack2(h0,h1); hi[1] = pack2(h2,h3);
    lo[0] = pack2(l0,l1); lo[1] = pack2(l2,l3);
}

// ---------------- cp.async helpers ----------------
__device__ __forceinline__ void cpa16(uint32_t smem, const void* g) {
    asm volatile("cp.async.cg.shared.global [%0], [%1], 16;" :: "r"(smem), "l"(g));
}
__device__ __forceinline__ void cpa_commit() {
    asm volatile("cp.async.commit_group;");
}
__device__ __forceinline__ void cpa_wait0() {
    asm volatile("cp.async.wait_group 0;");
}

// ---------------- LayerNorm ----------------
__global__ void ln_kernel(const float* __restrict__ x, const float* __restrict__ add,
                          const float* __restrict__ g, const float* __restrict__ b,
                          float* __restrict__ y, uint16_t* __restrict__ yh,
                          uint16_t* __restrict__ yl, int D) {
    int row = blockIdx.x;
    const float* xr = x + (size_t)row * D;
    const float* ar = add ? add + (size_t)row * D : nullptr;

    float s = 0.f, ss = 0.f;
    for (int i = threadIdx.x; i < D; i += blockDim.x) {
        float v = xr[i] + (ar ? ar[i] : 0.f);
        s += v; ss += v * v;
    }
    __shared__ float sh[66];
    #pragma unroll
    for (int o = 16; o; o >>= 1) {
        s  += __shfl_xor_sync(0xffffffffu, s, o);
        ss += __shfl_xor_sync(0xffffffffu, ss, o);
    }
    int w = threadIdx.x >> 5;
    if ((threadIdx.x & 31) == 0) { sh[w*2] = s; sh[w*2+1] = ss; }
    __syncthreads();
    int nw = blockDim.x >> 5;
    if (threadIdx.x < 32) {
        s  = threadIdx.x < nw ? sh[threadIdx.x*2]   : 0.f;
        ss = threadIdx.x < nw ? sh[threadIdx.x*2+1] : 0.f;
        #pragma unroll
        for (int o = 16; o; o >>= 1) {
            s  += __shfl_xor_sync(0xffffffffu, s, o);
            ss += __shfl_xor_sync(0xffffffffu, ss, o);
        }
        if (threadIdx.x == 0) { sh[64] = s; sh[65] = ss; }
    }
    __syncthreads();
    float mean = sh[64] / (float)D;
    float var  = sh[65] / (float)D - mean * mean;
    float inv  = rsqrtf(var + 1e-5f);
    for (int i = threadIdx.x; i < D; i += blockDim.x) {
        float v = xr[i] + (ar ? ar[i] : 0.f);
        float o = (v - mean) * inv * g[i] + b[i];
        if (y) y[(size_t)row * D + i] = o;
        if (yh) {
            uint16_t h, l;
            splitv(o, h, l);
            yh[(size_t)row * D + i] = h;
            yl[(size_t)row * D + i] = l;
        }
    }
}

// ---------------- weight split (n jobs via gridDim.y) ----------------
struct SplitJobs {
    const float* src[6];
    uint16_t* hi[6];
    uint16_t* lo[6];
    int n4[6];
};
__global__ void split_all(SplitJobs jobs) {
    int seg = blockIdx.y;
    int n4 = jobs.n4[seg];
    const float4* src = (const float4*)jobs.src[seg];
    uint2* hid = (uint2*)jobs.hi[seg];
    uint2* lod = (uint2*)jobs.lo[seg];
    for (int i = blockIdx.x * blockDim.x + threadIdx.x; i < n4;
         i += gridDim.x * blockDim.x) {
        float4 f = src[i];
        uint32_t h[2], l[2];
        split4(f.x, f.y, f.z, f.w, h, l);
        hid[i] = make_uint2(h[0], h[1]);
        lod[i] = make_uint2(l[0], l[1]);
    }
}

// ---------------- combine kernels ----------------
__global__ void combine_ao(const float* __restrict__ p, uint16_t* __restrict__ aoh,
                           uint16_t* __restrict__ aol, int n) {
    int i = blockIdx.x * blockDim.x + threadIdx.x;
    if (i < n) {
        float v = p[i] + p[n + i];
        uint16_t h, l;
        splitv(v, h, l);
        aoh[i] = h;
        aol[i] = l;
    }
}
__global__ void combine_w2(const float* __restrict__ p, const float* __restrict__ bias,
                           float* __restrict__ out, int n) {
    int i = blockIdx.x * blockDim.x + threadIdx.x;
    if (i < n) {
        out[i] = p[i] + p[n + i] + p[2*n + i] + p[3*n + i] + bias[i & (TD - 1)];
    }
}

// ================== tensor-core primitives ==================
__device__ __forceinline__ void ldsm4(uint32_t& r0, uint32_t& r1, uint32_t& r2, uint32_t& r3,
                                      uint32_t addr) {
    asm volatile("ldmatrix.sync.aligned.m8n8.x4.shared.b16 {%0,%1,%2,%3}, [%4];"
        : "=r"(r0), "=r"(r1), "=r"(r2), "=r"(r3) : "r"(addr));
}
__device__ __forceinline__ void ldsm4t(uint32_t& r0, uint32_t& r1, uint32_t& r2, uint32_t& r3,
                                       uint32_t addr) {
    asm volatile("ldmatrix.sync.aligned.m8n8.x4.trans.shared.b16 {%0,%1,%2,%3}, [%4];"
        : "=r"(r0), "=r"(r1), "=r"(r2), "=r"(r3) : "r"(addr));
}
__device__ __forceinline__ void mma16816(float* c, const uint32_t* a, uint32_t b0, uint32_t b1) {
    asm volatile(
        "mma.sync.aligned.m16n8k16.row.col.f32.bf16.bf16.f32 "
        "{%0,%1,%2,%3},{%4,%5,%6,%7},{%8,%9},{%0,%1,%2,%3};"
        : "+f"(c[0]), "+f"(c[1]), "+f"(c[2]), "+f"(c[3])
        : "r"(a[0]), "r"(a[1]), "r"(a[2]), "r"(a[3]), "r"(b0), "r"(b1));
}

// ============ cp.async 2-stage pre-split GEMM (R11-proven) ============
template<int BM, int MODE>
__global__ __launch_bounds__(256) void mma_gemm_db(
        const uint16_t* __restrict__ Ah, const uint16_t* __restrict__ Al,
        const uint16_t* __restrict__ Wh, const uint16_t* __restrict__ Wl,
        const float* __restrict__ bias, float* __restrict__ Cf,
        uint16_t* __restrict__ Ch, uint16_t* __restrict__ Cl,
        int M, int N, int K, int T) {
    constexpr int BN = 64;
    constexpr int WM = BM / 2;
    constexpr int MT = WM / 16;
    constexpr int NT = 2;
    constexpr int SA = 40, SB = 72;
    constexpr int ATH = BM * 4;

    __shared__ uint16_t As[2][2][BM * SA];
    __shared__ uint16_t Bs[2][2][32 * SB];

    int tid = threadIdx.x;
    int l = tid & 31, w = tid >> 5;
    int wm = w >> 2, wn = w & 3;
    int m0 = blockIdx.y * BM, n0 = blockIdx.x * BN;
    int koff = (MODE == 3) ? blockIdx.z * T : 0;
    int Kloop = (MODE == 3) ? T : K;

    int arow = tid >> 2, aseg = (tid & 3) * 8;
    int bk = tid >> 3, bn = (tid & 7) * 8;

    uint32_t asb[2][2], bsb[2][2];
    #pragma unroll
    for (int s = 0; s < 2; s++) {
        #pragma unroll
        for (int p = 0; p < 2; p++) {
            asb[s][p] = (uint32_t)__cvta_generic_to_shared(&As[s][p][0]);
            bsb[s][p] = (uint32_t)__cvta_generic_to_shared(&Bs[s][p][0]);
        }
    }
    uint32_t aoff = (uint32_t)((arow * SA + aseg) * 2);
    uint32_t boff = (uint32_t)((bk * SB + bn) * 2);

    uint32_t aAddr[MT];
    #pragma unroll
    for (int mt = 0; mt < MT; mt++) {
        int row = wm * WM + mt * 16 + (l & 15);
        aAddr[mt] = (uint32_t)((row * SA + (l >> 4) * 8) * 2);
    }
    uint32_t bAddr;
    {
        int kk = (l & 7) + ((l >> 3) & 1) * 8;
        int nn = wn * 16 + (l >> 4) * 8;
        bAddr = (uint32_t)((kk * SB + nn) * 2);
    }

    float acc[MT][NT][4];
    #pragma unroll
    for (int mt = 0; mt < MT; mt++)
        #pragma unroll
        for (int nt = 0; nt < NT; nt++)
            #pragma unroll
            for (int i = 0; i < 4; i++) acc[mt][nt][i] = 0.f;

    auto issue = [&](int stage, int k0) {
        if (ATH == 256 || tid < ATH) {
            cpa16(asb[stage][0] + aoff, Ah + (size_t)(m0 + arow) * K + koff + k0 + aseg);
            cpa16(asb[stage][1] + aoff, Al + (size_t)(m0 + arow) * K + koff + k0 + aseg);
        }
        cpa16(bsb[stage][0] + boff, Wh + (size_t)(koff + k0 + bk) * N + n0 + bn);
        cpa16(bsb[stage][1] + boff, Wl + (size_t)(koff + k0 + bk) * N + n0 + bn);
        cpa_commit();
    };

    int nch = Kloop / 32;
    issue(0, 0);
    for (int c = 0; c < nch; c++) {
        cpa_wait0();
        __syncthreads();
        if (c + 1 < nch) issue((c + 1) & 1, (c + 1) * 32);
        int st = c & 1;

        #pragma unroll
        for (int ks = 0; ks < 32; ks += 16) {
            uint32_t aHi[MT][4], aLo[MT][4];
            #pragma unroll
            for (int mt = 0; mt < MT; mt++) {
                ldsm4(aHi[mt][0], aHi[mt][1], aHi[mt][2], aHi[mt][3],
                      asb[st][0] + aAddr[mt] + ks * 2);
                ldsm4(aLo[mt][0], aLo[mt][1], aLo[mt][2], aLo[mt][3],
                      asb[st][1] + aAddr[mt] + ks * 2);
            }
            uint32_t bh[4], bl[4];
            ldsm4t(bh[0], bh[1], bh[2], bh[3], bsb[st][0] + bAddr + ks * SB * 2);
            ldsm4t(bl[0], bl[1], bl[2], bl[3], bsb[st][1] + bAddr + ks * SB * 2);
            #pragma unroll
            for (int q = 0; q < 2; q++) {
                #pragma unroll
                for (int mt = 0; mt < MT; mt++) {
                    mma16816(acc[mt][q], aHi[mt], bh[2*q], bh[2*q+1]);
                    mma16816(acc[mt][q], aHi[mt], bl[2*q], bl[2*q+1]);
                    mma16816(acc[mt][q], aLo[mt], bh[2*q], bh[2*q+1]);
                }
            }
        }
        __syncthreads();
    }

    #pragma unroll
    for (int mt = 0; mt < MT; mt++) {
        int row0 = m0 + wm * WM + mt * 16 + (l >> 2);
        #pragma unroll
        for (int nt = 0; nt < NT; nt++) {
            int col = n0 + wn * 16 + nt * 8 + (l & 3) * 2;
            if (MODE == 3) {
                float* dst = Cf + (size_t)blockIdx.z * M * N;
                *(float2*)(dst + (size_t)row0 * N + col) =
                    make_float2(acc[mt][nt][0], acc[mt][nt][1]);
                *(float2*)(dst + (size_t)(row0 + 8) * N + col) =
                    make_float2(acc[mt][nt][2], acc[mt][nt][3]);
                continue;
            }
            float b0 = bias[col], b1 = bias[col + 1];
            float v00 = acc[mt][nt][0] + b0, v01 = acc[mt][nt][1] + b1;
            float v10 = acc[mt][nt][2] + b0, v11 = acc[mt][nt][3] + b1;
            if (MODE == 2) {
                v00 = 0.5f * v00 * (1.f + erff(v00 * 0.70710678118654752f));
                v01 = 0.5f * v01 * (1.f + erff(v01 * 0.70710678118654752f));
                v10 = 0.5f * v10 * (1.f + erff(v10 * 0.70710678118654752f));
                v11 = 0.5f * v11 * (1.f + erff(v11 * 0.70710678118654752f));
            }
            if (MODE == 0) {
                *(float2*)(Cf + (size_t)row0 * N + col)       = make_float2(v00, v01);
                *(float2*)(Cf + (size_t)(row0 + 8) * N + col) = make_float2(v10, v11);
            } else {
                uint16_t h00,l00,h01,l01,h10,l10,h11,l11;
                splitv(v00,h00,l00); splitv(v01,h01,l01);
                splitv(v10,h10,l10); splitv(v11,h11,l11);
                size_t i0x, i1x;
                if (MODE == 1) {
                    int h = col >> 6, d = col & 63;
                    int bi0 = row0 / T, t0 = row0 % T;
                    int bi1 = (row0 + 8) / T, t1 = (row0 + 8) % T;
                    i0x = (size_t)((bi0*HH + h)*T + t0)*HD + d;
                    i1x = (size_t)((bi1*HH + h)*T + t1)*HD + d;
                } else {
                    i0x = (size_t)row0 * N + col;
                    i1x = (size_t)(row0 + 8) * N + col;
                }
                *(ushort2*)(Ch + i0x) = make_ushort2(h00, h01);
                *(ushort2*)(Cl + i0x) = make_ushort2(l00, l01);
                *(ushort2*)(Ch + i1x) = make_ushort2(h10, h11);
                *(ushort2*)(Cl + i1x) = make_ushort2(l10, l11);
            }
        }
    }
}

// ================== attention pass A (jz-split x4, R11-proven) ==================
__global__ __launch_bounds__(256) void attn_scores_mma(
        const uint16_t* __restrict__ qh, const uint16_t* __restrict__ ql,
        const uint16_t* __restrict__ kh_, const uint16_t* __restrict__ kl_,
        const float* __restrict__ edge_emb, const float* __restrict__ ep_w,
        const float* __restrict__ ep_b,
        float* __restrict__ logits, float* __restrict__ gm2, float* __restrict__ gz2) {
    __shared__ uint16_t Qhi[64*72], Qlo[64*72];
    __shared__ uint16_t Khi[64*72], Klo[64*72];
    __shared__ float m_sh[2][64], l_sh[2][64];
    __shared__ float s_scale;

    int tid = threadIdx.x, l = tid & 31, w = tid >> 5;
    int wm = w >> 1, wn = w & 1;
    int bh = blockIdx.y, i0 = blockIdx.x * 64;
    int jz = blockIdx.z;
    int hidx = bh & (HH-1);
    const uint16_t* qhb = qh + ((size_t)bh * SS + i0) * HD;
    const uint16_t* qlb = ql + ((size_t)bh * SS + i0) * HD;
    const uint16_t* khb = kh_ + (size_t)bh * PP * HD;
    const uint16_t* klb = kl_ + (size_t)bh * PP * HD;
    float* lb = logits + ((size_t)bh * SS + i0) * PP;
    float epb = ep_b[0];

    if (tid < 32) {
        float a = edge_emb[hidx*32 + tid] * ep_w[tid];
        #pragma unroll
        for (int o = 16; o; o >>= 1) a += __shfl_xor_sync(0xffffffffu, a, o);
        if (tid == 0) s_scale = a;
    }

    int lrow = tid >> 2, lseg = (tid & 3) * 16;
    {
        const uint16_t* s = qhb + (size_t)lrow * HD + lseg;
        *(uint4*)&Qhi[lrow*72 + lseg]     = *(const uint4*)(s);
        *(uint4*)&Qhi[lrow*72 + lseg + 8] = *(const uint4*)(s + 8);
        s = qlb + (size_t)lrow * HD + lseg;
        *(uint4*)&Qlo[lrow*72 + lseg]     = *(const uint4*)(s);
        *(uint4*)&Qlo[lrow*72 + lseg + 8] = *(const uint4*)(s + 8);
    }

    uint32_t aHiB = (uint32_t)__cvta_generic_to_shared(Qhi);
    uint32_t aLoB = (uint32_t)__cvta_generic_to_shared(Qlo);
    uint32_t bHiB = (uint32_t)__cvta_generic_to_shared(Khi);
    uint32_t bLoB = (uint32_t)__cvta_generic_to_shared(Klo);

    uint32_t aAddr = (uint32_t)(((wm*16 + (l & 15)) * 72 + (l >> 4) * 8) * 2);
    uint32_t bAddr[2];
    #pragma unroll
    for (int p = 0; p < 2; p++)
        bAddr[p] = (uint32_t)(((wn*32 + p*16 + (l & 15)) * 72 + (l >> 4) * 8) * 2);

    float m_run[2] = {-1e30f, -1e30f};
    float l_run[2] = {0.f, 0.f};

    int jstart = jz * (PP/4), jend = (jz + 1) * (PP/4);

    uint4 rh0, rh1, rl0, rl1;
    {
        const uint16_t* s = khb + (size_t)(jstart + lrow) * HD + lseg;
        rh0 = *(const uint4*)(s); rh1 = *(const uint4*)(s + 8);
        s = klb + (size_t)(jstart + lrow) * HD + lseg;
        rl0 = *(const uint4*)(s); rl1 = *(const uint4*)(s + 8);
    }

    for (int j0 = jstart; j0 < jend; j0 += 64) {
        __syncthreads();
        *(uint4*)&Khi[lrow*72 + lseg]     = rh0;
        *(uint4*)&Khi[lrow*72 + lseg + 8] = rh1;
        *(uint4*)&Klo[lrow*72 + lseg]     = rl0;
        *(uint4*)&Klo[lrow*72 + lseg + 8] = rl1;
        __syncthreads();
        if (j0 + 64 < jend) {
            const uint16_t* s = khb + (size_t)(j0 + 64 + lrow) * HD + lseg;
            rh0 = *(const uint4*)(s); rh1 = *(const uint4*)(s + 8);
            s = klb + (size_t)(j0 + 64 + lrow) * HD + lseg;
            rl0 = *(const uint4*)(s); rl1 = *(const uint4*)(s + 8);
        }

        float acc[4][4];
        #pragma unroll
        for (int nt = 0; nt < 4; nt++)
            #pragma unroll
            for (int i = 0; i < 4; i++) acc[nt][i] = 0.f;

        #pragma unroll
        for (int ks = 0; ks < 64; ks += 16) {
            uint32_t ah[4], al[4];
            ldsm4(ah[0], ah[1], ah[2], ah[3], aHiB + aAddr + ks * 2);
            ldsm4(al[0], al[1], al[2], al[3], aLoB + aAddr + ks * 2);
            #pragma unroll
            for (int p = 0; p < 2; p++) {
                uint32_t kh[4], kl[4];
                ldsm4(kh[0], kh[1], kh[2], kh[3], bHiB + bAddr[p] + ks * 2);
                ldsm4(kl[0], kl[1], kl[2], kl[3], bLoB + bAddr[p] + ks * 2);
                mma16816(acc[2*p],   ah, kh[0], kh[2]);
                mma16816(acc[2*p],   ah, kl[0], kl[2]);
                mma16816(acc[2*p],   al, kh[0], kh[2]);
                mma16816(acc[2*p+1], ah, kh[1], kh[3]);
                mma16816(acc[2*p+1], ah, kl[1], kl[3]);
                mma16816(acc[2*p+1], al, kh[1], kh[3]);
            }
        }

        float sh_scale = s_scale;
        int r0 = wm*16 + (l >> 2);
        #pragma unroll
        for (int nt = 0; nt < 4; nt++) {
            int noff = wn*32 + (nt >> 1)*16 + (nt & 1)*8 + (l & 3)*2;
            #pragma unroll
            for (int i = 0; i < 4; i++) {
                float sc = acc[nt][i] * 0.125f;
                float t = fmaf(sc, sh_scale, epb);
                acc[nt][i] = sc + (t > 0.f ? t : 0.2f * t);
            }
            *(float2*)(lb + (size_t)r0 * PP + j0 + noff)       = make_float2(acc[nt][0], acc[nt][1]);
            *(float2*)(lb + (size_t)(r0 + 8) * PP + j0 + noff) = make_float2(acc[nt][2], acc[nt][3]);
        }
        #pragma unroll
        for (int r = 0; r < 2; r++) {
            float tm = -1e30f;
            #pragma unroll
            for (int nt = 0; nt < 4; nt++)
                tm = fmaxf(tm, fmaxf(acc[nt][2*r], acc[nt][2*r+1]));
            tm = fmaxf(tm, __shfl_xor_sync(0xffffffffu, tm, 1));
            tm = fmaxf(tm, __shfl_xor_sync(0xffffffffu, tm, 2));
            float nm = fmaxf(m_run[r], tm);
            float pe = 0.f;
            #pragma unroll
            for (int nt = 0; nt < 4; nt++)
                pe += fexp(acc[nt][2*r] - nm) + fexp(acc[nt][2*r+1] - nm);
            pe += __shfl_xor_sync(0xffffffffu, pe, 1);
            pe += __shfl_xor_sync(0xffffffffu, pe, 2);
            l_run[r] = l_run[r] * fexp(m_run[r] - nm) + pe;
            m_run[r] = nm;
        }
    }

    if ((l & 3) == 0) {
        int r0 = wm*16 + (l >> 2);
        m_sh[wn][r0]   = m_run[0];  l_sh[wn][r0]   = l_run[0];
        m_sh[wn][r0+8] = m_run[1];  l_sh[wn][r0+8] = l_run[1];
    }
    __syncthreads();
    if (tid < 64) {
        float m0 = m_sh[0][tid], m1 = m_sh[1][tid];
        float M = fmaxf(m0, m1);
        float Z = l_sh[0][tid] * fexp(m0 - M) + l_sh[1][tid] * fexp(m1 - M);
        size_t idx = (size_t)jz * (BB*HH*SS) + (size_t)bh*SS + i0 + tid;
        gm2[idx] = M;
        gz2[idx] = Z;
    }
}

// ================== attention pass B (j-split x2, R11-proven) ==================
__global__ __launch_bounds__(256) void attn_pv_mma(
        const uint16_t* __restrict__ vh_, const uint16_t* __restrict__ vl_,
        const float* __restrict__ gm2, const float* __restrict__ gz2,
        float* __restrict__ attn, float* __restrict__ aop) {
    __shared__ uint16_t Phi[32*72], Plo[32*72];
    __shared__ uint16_t Vhi[64*72], Vlo[64*72];
    __shared__ float sm_m[32], sm_iz[32];

    int tid = threadIdx.x, l = tid & 31, w = tid >> 5;
    int wm = w >> 2, wn = w & 3;
    int bh = blockIdx.y;
    int b = bh >> 3, h = bh & 7;
    int i0 = blockIdx.x * 32;
    int jz = blockIdx.z;
    float* ab = attn + ((size_t)bh * SS + i0) * PP;
    const uint16_t* vhb = vh_ + (size_t)bh * PP * HD;
    const uint16_t* vlb = vl_ + (size_t)bh * PP * HD;

    if (tid < 32) {
        size_t idx = (size_t)bh*SS + i0 + tid;
        const size_t STR = (size_t)(BB*HH*SS);
        float m0 = gm2[idx], m1 = gm2[STR + idx];
        float m2 = gm2[2*STR + idx], m3 = gm2[3*STR + idx];
        float M = fmaxf(fmaxf(m0, m1), fmaxf(m2, m3));
        float Z = gz2[idx] * fexp(m0 - M) + gz2[STR + idx] * fexp(m1 - M)
                + gz2[2*STR + idx] * fexp(m2 - M) + gz2[3*STR + idx] * fexp(m3 - M);
        sm_m[tid]  = M;
        sm_iz[tid] = 1.f / Z;
    }

    uint32_t aHiB = (uint32_t)__cvta_generic_to_shared(Phi);
    uint32_t aLoB = (uint32_t)__cvta_generic_to_shared(Plo);
    uint32_t bHiB = (uint32_t)__cvta_generic_to_shared(Vhi);
    uint32_t bLoB = (uint32_t)__cvta_generic_to_shared(Vlo);

    uint32_t aAddr = (uint32_t)(((wm*16 + (l & 15)) * 72 + (l >> 4) * 8) * 2);
    uint32_t bAddr;
    {
        int kk = (l & 7) + ((l >> 3) & 1) * 8;
        int nn = wn*16 + (l >> 4) * 8;
        bAddr = (uint32_t)((kk * 72 + nn) * 2);
    }

    float acc[2][4];
    #pragma unroll
    for (int q = 0; q < 2; q++)
        #pragma unroll
        for (int i = 0; i < 4; i++) acc[q][i] = 0.f;

    int prow = tid >> 3, pseg = (tid & 7) * 8;
    int vrow = tid >> 2, vseg = (tid & 3) * 16;

    int jstart = jz * (PP/2), jend = (jz + 1) * (PP/2);

    float4 pf0, pf1;
    uint4 rvh0, rvh1, rvl0, rvl1;
    {
        const float* src = ab + (size_t)prow * PP + jstart + pseg;
        pf0 = *(const float4*)(src);
        pf1 = *(const float4*)(src + 4);
        const uint16_t* s = vhb + (size_t)(jstart + vrow) * HD + vseg;
        rvh0 = *(const uint4*)(s); rvh1 = *(const uint4*)(s + 8);
        s = vlb + (size_t)(jstart + vrow) * HD + vseg;
        rvl0 = *(const uint4*)(s); rvl1 = *(const uint4*)(s + 8);
    }

    for (int j0 = jstart; j0 < jend; j0 += 64) {
        __syncthreads();
        {
            float m = sm_m[prow], iz = sm_iz[prow];
            float pv[8];
            pv[0] = fexp(pf0.x - m) * iz; pv[1] = fexp(pf0.y - m) * iz;
            pv[2] = fexp(pf0.z - m) * iz; pv[3] = fexp(pf0.w - m) * iz;
            pv[4] = fexp(pf1.x - m) * iz; pv[5] = fexp(pf1.y - m) * iz;
            pv[6] = fexp(pf1.z - m) * iz; pv[7] = fexp(pf1.w - m) * iz;
            float* dst = ab + (size_t)prow * PP + j0 + pseg;
            *(float4*)(dst)     = make_float4(pv[0], pv[1], pv[2], pv[3]);
            *(float4*)(dst + 4) = make_float4(pv[4], pv[5], pv[6], pv[7]);
            uint32_t hi[4], lo[4];
            split4(pv[0], pv[1], pv[2], pv[3], hi,     lo);
            split4(pv[4], pv[5], pv[6], pv[7], hi + 2, lo + 2);
            *(uint4*)&Phi[prow*72 + pseg] = *(uint4*)hi;
            *(uint4*)&Plo[prow*72 + pseg] = *(uint4*)lo;
        }
        *(uint4*)&Vhi[vrow*72 + vseg]     = rvh0;
        *(uint4*)&Vhi[vrow*72 + vseg + 8] = rvh1;
        *(uint4*)&Vlo[vrow*72 + vseg]     = rvl0;
        *(uint4*)&Vlo[vrow*72 + vseg + 8] = rvl1;
        __syncthreads();
        if (j0 + 64 < jend) {
            const float* src = ab + (size_t)prow * PP + j0 + 64 + pseg;
            pf0 = *(const float4*)(src);
            pf1 = *(const float4*)(src + 4);
            const uint16_t* s = vhb + (size_t)(j0 + 64 + vrow) * HD + vseg;
            rvh0 = *(const uint4*)(s); rvh1 = *(const uint4*)(s + 8);
            s = vlb + (size_t)(j0 + 64 + vrow) * HD + vseg;
            rvl0 = *(const uint4*)(s); rvl1 = *(const uint4*)(s + 8);
        }

        #pragma unroll
        for (int ks = 0; ks < 64; ks += 16) {
            uint32_t ah[4], al[4];
            ldsm4(ah[0], ah[1], ah[2], ah[3], aHiB + aAddr + ks * 2);
            ldsm4(al[0], al[1], al[2], al[3], aLoB + aAddr + ks * 2);
            uint32_t vh[4], vl[4];
            ldsm4t(vh[0], vh[1], vh[2], vh[3], bHiB + bAddr + ks * 72 * 2);
            ldsm4t(vl[0], vl[1], vl[2], vl[3], bLoB + bAddr + ks * 72 * 2);
            #pragma unroll
            for (int q = 0; q < 2; q++) {
                mma16816(acc[q], ah, vh[2*q], vh[2*q+1]);
                mma16816(acc[q], ah, vl[2*q], vl[2*q+1]);
                mma16816(acc[q], al, vh[2*q], vh[2*q+1]);
            }
        }
    }

    float* dst = aop + (size_t)jz * OUT_ELEMS;
    int r0 = i0 + wm*16 + (l >> 2);
    #pragma unroll
    for (int q = 0; q < 2; q++) {
        int col = h*HD + wn*16 + q*8 + (l & 3)*2;
        *(float2*)(dst + (size_t)(b*SS + r0) * TD + col)     = make_float2(acc[q][0], acc[q][1]);
        *(float2*)(dst + (size_t)(b*SS + r0 + 8) * TD + col) = make_float2(acc[q][2], acc[q][3]);
    }
}

// ---------------- launch ----------------
extern "C" void kernel_launch(void* const* d_in, const int* in_sizes, int n_in,
                              void* d_out, int out_size) {
    const float* text  = (const float*)d_in[0];
    const float* shape = (const float*)d_in[1];
    const float* tn_g = (const float*)d_in[2];
    const float* tn_b = (const float*)d_in[3];
    const float* sn_g = (const float*)d_in[4];
    const float* sn_b = (const float*)d_in[5];
    const float* Wq = (const float*)d_in[6];
    const float* bq = (const float*)d_in[7];
    const float* Wk = (const float*)d_in[8];
    const float* bk = (const float*)d_in[9];
    const float* Wv = (const float*)d_in[10];
    const float* bv = (const float*)d_in[11];
    const float* edge_emb = (const float*)d_in[12];
    const float* ep_w = (const float*)d_in[13];
    const float* ep_b = (const float*)d_in[14];
    const float* Wo = (const float*)d_in[15];
    const float* bo = (const float*)d_in[16];
    const float* on_g = (const float*)d_in[17];
    const float* on_b = (const float*)d_in[18];
    const float* W1 = (const float*)d_in[19];
    const float* b1 = (const float*)d_in[20];
    const float* W2 = (const float*)d_in[21];
    const float* b2 = (const float*)d_in[22];
    const float* fn_g = (const float*)d_in[23];
    const float* fn_b = (const float*)d_in[24];

    float* out_final = (float*)d_out;
    float* attn_buf  = (float*)d_out + OUT_ELEMS;

    uint16_t *p_tnh,*p_tnl,*p_snh,*p_snl,*p_qh,*p_ql,*p_kh,*p_kl,*p_vh,*p_vl;
    uint16_t *p_aoh,*p_aol,*p_o1h,*p_o1l,*p_hidh,*p_hidl;
    uint16_t *p_wqh,*p_wql,*p_wkh,*p_wkl,*p_wvh,*p_wvl,*p_woh,*p_wol,*p_w1h,*p_w1l,*p_w2h,*p_w2l;
    float *p_m2,*p_z2,*p_o1,*p_tmp,*p_aop,*p_w2p;
    cudaGetSymbolAddress((void**)&p_tnh, g_tnh); cudaGetSymbolAddress((void**)&p_tnl, g_tnl);
    cudaGetSymbolAddress((void**)&p_snh, g_snh); cudaGetSymbolAddress((void**)&p_snl, g_snl);
    cudaGetSymbolAddress((void**)&p_qh, g_qh);   cudaGetSymbolAddress((void**)&p_ql, g_ql);
    cudaGetSymbolAddress((void**)&p_kh, g_kh);   cudaGetSymbolAddress((void**)&p_kl, g_kl);
    cudaGetSymbolAddress((void**)&p_vh, g_vh);   cudaGetSymbolAddress((void**)&p_vl, g_vl);
    cudaGetSymbolAddress((void**)&p_aoh, g_aoh); cudaGetSymbolAddress((void**)&p_aol, g_aol);
    cudaGetSymbolAddress((void**)&p_o1h, g_o1h); cudaGetSymbolAddress((void**)&p_o1l, g_o1l);
    cudaGetSymbolAddress((void**)&p_hidh, g_hidh); cudaGetSymbolAddress((void**)&p_hidl, g_hidl);
    cudaGetSymbolAddress((void**)&p_wqh, g_wqh); cudaGetSymbolAddress((void**)&p_wql, g_wql);
    cudaGetSymbolAddress((void**)&p_wkh, g_wkh); cudaGetSymbolAddress((void**)&p_wkl, g_wkl);
    cudaGetSymbolAddress((void**)&p_wvh, g_wvh); cudaGetSymbolAddress((void**)&p_wvl, g_wvl);
    cudaGetSymbolAddress((void**)&p_woh, g_woh); cudaGetSymbolAddress((void**)&p_wol, g_wol);
    cudaGetSymbolAddress((void**)&p_w1h, g_w1h); cudaGetSymbolAddress((void**)&p_w1l, g_w1l);
    cudaGetSymbolAddress((void**)&p_w2h, g_w2h); cudaGetSymbolAddress((void**)&p_w2l, g_w2l);
    cudaGetSymbolAddress((void**)&p_m2, g_m2);   cudaGetSymbolAddress((void**)&p_z2, g_z2);
    cudaGetSymbolAddress((void**)&p_o1, g_out1); cudaGetSymbolAddress((void**)&p_tmp, g_tmp);
    cudaGetSymbolAddress((void**)&p_aop, g_aop); cudaGetSymbolAddress((void**)&p_w2p, g_w2p);

    static cudaStream_t s1 = nullptr, s2 = nullptr;
    static cudaEvent_t ev[7];
    if (!s1) {
        cudaStreamCreateWithFlags(&s1, cudaStreamNonBlocking);
        cudaStreamCreateWithFlags(&s2, cudaStreamNonBlocking);
        for (int i = 0; i < 7; i++)
            cudaEventCreateWithFlags(&ev[i], cudaEventDisableTiming);
    }

    // split1 (critical: QKV weights), split2 (deferred: Wo/W1/W2)
    SplitJobs j1;
    j1.src[0]=Wq; j1.hi[0]=p_wqh; j1.lo[0]=p_wql; j1.n4[0]=TD*TD/4;
    j1.src[1]=Wk; j1.hi[1]=p_wkh; j1.lo[1]=p_wkl; j1.n4[1]=SD*TD/4;
    j1.src[2]=Wv; j1.hi[2]=p_wvh; j1.lo[2]=p_wvl; j1.n4[2]=SD*TD/4;
    SplitJobs j2;
    j2.src[0]=Wo; j2.hi[0]=p_woh; j2.lo[0]=p_wol; j2.n4[0]=TD*TD/4;
    j2.src[1]=W1; j2.hi[1]=p_w1h; j2.lo[1]=p_w1l; j2.n4[1]=TD*FF/4;
    j2.src[2]=W2; j2.hi[2]=p_w2h; j2.lo[2]=p_w2l; j2.n4[2]=FF*TD/4;

    // ---- fork 1: split1 (0) || ln text (s1) || ln shape + deferred split2 (s2) ----
    cudaEventRecord(ev[0], 0);
    cudaStreamWaitEvent(s1, ev[0], 0);
    cudaStreamWaitEvent(s2, ev[0], 0);
    split_all<<<dim3(256, 3), 256, 0, 0>>>(j1);
    ln_kernel<<<NROW_T, 128, 0, s1>>>(text, nullptr, tn_g, tn_b, nullptr, p_tnh, p_tnl, TD);
    ln_kernel<<<NROW_S, 128, 0, s2>>>(shape, nullptr, sn_g, sn_b, nullptr, p_snh, p_snl, SD);
    cudaEventRecord(ev[1], s1);
    cudaEventRecord(ev[2], s2);
    cudaStreamWaitEvent(0, ev[1], 0);
    cudaStreamWaitEvent(0, ev[2], 0);
    // deferred weight split runs on s2 behind ln_shape (V gemm follows it on s2)
    split_all<<<dim3(256, 3), 256, 0, s2>>>(j2);
    cudaEventRecord(ev[6], s2);

    // ---- fork 2: Q (0) || K (s1) || V (s2, after split2) ----
    cudaEventRecord(ev[3], 0);
    cudaStreamWaitEvent(s1, ev[3], 0);
    cudaStreamWaitEvent(s2, ev[3], 0);
    mma_gemm_db<32,1><<<dim3(TD/64, NROW_T/32), 256, 0, 0>>>(
        p_tnh, p_tnl, p_wqh, p_wql, bq, nullptr, p_qh, p_ql, NROW_T, TD, TD, SS);
    mma_gemm_db<64,1><<<dim3(TD/64, NROW_S/64), 256, 0, s1>>>(
        p_snh, p_snl, p_wkh, p_wkl, bk, nullptr, p_kh, p_kl, NROW_S, TD, SD, PP);
    mma_gemm_db<64,1><<<dim3(TD/64, NROW_S/64), 256, 0, s2>>>(
        p_snh, p_snl, p_wvh, p_wvl, bv, nullptr, p_vh, p_vl, NROW_S, TD, SD, PP);
    cudaEventRecord(ev[4], s1);   // K done
    cudaEventRecord(ev[5], s2);   // V done

    // ---- pass A needs Q (stream 0) + K ----
    cudaStreamWaitEvent(0, ev[4], 0);
    attn_scores_mma<<<dim3(SS/64, BB*HH, 4), 256, 0, 0>>>(p_qh, p_ql, p_kh, p_kl,
                                                          edge_emb, ep_w, ep_b,
                                                          attn_buf, p_m2, p_z2);
    // ---- pass B additionally needs V ----
    cudaStreamWaitEvent(0, ev[5], 0);
    attn_pv_mma<<<dim3(SS/32, BB*HH, 2), 256, 0, 0>>>(p_vh, p_vl, p_m2, p_z2, attn_buf, p_aop);
    combine_ao<<<(OUT_ELEMS + 255)/256, 256, 0, 0>>>(p_aop, p_aoh, p_aol, OUT_ELEMS);

    // ---- serial tail (join deferred weight split first) ----
    cudaStreamWaitEvent(0, ev[6], 0);
    mma_gemm_db<32,0><<<dim3(TD/64, NROW_T/32), 256, 0, 0>>>(
        p_aoh, p_aol, p_woh, p_wol, bo, p_tmp, nullptr, nullptr, NROW_T, TD, TD, 0);
    ln_kernel<<<NROW_T, 128, 0, 0>>>(text, p_tmp, on_g, on_b, p_o1, p_o1h, p_o1l, TD);

    mma_gemm_db<32,2><<<dim3(FF/64, NROW_T/32), 256, 0, 0>>>(
        p_o1h, p_o1l, p_w1h, p_w1l, b1, nullptr, p_hidh, p_hidl, NROW_T, FF, TD, 0);
    mma_gemm_db<32,3><<<dim3(TD/64, NROW_T/32, 4), 256, 0, 0>>>(
        p_hidh, p_hidl, p_w2h, p_w2l, b2, p_w2p, nullptr, nullptr, NROW_T, TD, FF, FF/4);
    combine_w2<<<(OUT_ELEMS + 255)/256, 256, 0, 0>>>(p_w2p, b2, p_tmp, OUT_ELEMS);
    ln_kernel<<<NROW_T, 128, 0, 0>>>(p_o1, p_tmp, fn_g, fn_b, out_final, nullptr, nullptr, TD);
}